// round 15
// baseline (speedup 1.0000x reference)
#include <cuda_runtime.h>
#include <cuda_bf16.h>
#include <math.h>
#include <stdint.h>

#define HID   256
#define NB    4096
#define NN    204800
#define HF4   1024
#define INV_SCALE 0.17677669529663687f
#define MAXSEG 1024

// ---------------- scratch (static device globals; no allocation) ----------------
__device__ float g_wkT[HID * HID];
__device__ float g_M  [HID * HID];
__device__ float g_rvec[HID];
__device__ float g_wcvec[HID];
__device__ float g_c0;
__device__ float g_escore[NN];        // overflow fallback only
__device__ float g_s [NB * HID];
__device__ float g_x1[NB * HID];
__device__ float g_h1[NB * HF4];
__device__ float g_hp[4 * NB * HID];  // split-K partials (U, Dh, FFN2 - sequential reuse)

// ---------------- helpers ----------------
__device__ __forceinline__ float warp_sum(float v) {
#pragma unroll
    for (int o = 16; o; o >>= 1) v += __shfl_xor_sync(0xffffffffu, v, o);
    return v;
}

__device__ __forceinline__ float block_sum_256(float v) {
    __shared__ float sh[8];
    int lane = threadIdx.x & 31, w = threadIdx.x >> 5;
    v = warp_sum(v);
    if (lane == 0) sh[w] = v;
    __syncthreads();
    float r = (lane < 8) ? sh[lane] : 0.f;
    r = warp_sum(r);
    __syncthreads();
    return r;
}

__device__ __forceinline__ uint32_t s2u(const void* p) {
    return (uint32_t)__cvta_generic_to_shared(p);
}

__device__ __forceinline__ void ldsm4(uint32_t& r0, uint32_t& r1, uint32_t& r2, uint32_t& r3, uint32_t addr) {
    asm volatile("ldmatrix.sync.aligned.m8n8.x4.shared.b16 {%0,%1,%2,%3}, [%4];"
                 : "=r"(r0), "=r"(r1), "=r"(r2), "=r"(r3) : "r"(addr));
}
__device__ __forceinline__ void ldsm4t(uint32_t& r0, uint32_t& r1, uint32_t& r2, uint32_t& r3, uint32_t addr) {
    asm volatile("ldmatrix.sync.aligned.m8n8.x4.trans.shared.b16 {%0,%1,%2,%3}, [%4];"
                 : "=r"(r0), "=r"(r1), "=r"(r2), "=r"(r3) : "r"(addr));
}
__device__ __forceinline__ void mma16816(float* c, const uint32_t* a, const uint32_t* b) {
    asm volatile("mma.sync.aligned.m16n8k16.row.col.f32.bf16.bf16.f32 "
                 "{%0,%1,%2,%3},{%4,%5,%6,%7},{%8,%9},{%0,%1,%2,%3};"
                 : "+f"(c[0]), "+f"(c[1]), "+f"(c[2]), "+f"(c[3])
                 : "r"(a[0]), "r"(a[1]), "r"(a[2]), "r"(a[3]), "r"(b[0]), "r"(b[1]));
}

__device__ __forceinline__ void split4(float4 v, uint2& h, uint2& l) {
    __nv_bfloat16 h0 = __float2bfloat16(v.x), h1 = __float2bfloat16(v.y);
    __nv_bfloat16 h2 = __float2bfloat16(v.z), h3 = __float2bfloat16(v.w);
    __nv_bfloat16 l0 = __float2bfloat16(v.x - __bfloat162float(h0));
    __nv_bfloat16 l1 = __float2bfloat16(v.y - __bfloat162float(h1));
    __nv_bfloat16 l2 = __float2bfloat16(v.z - __bfloat162float(h2));
    __nv_bfloat16 l3 = __float2bfloat16(v.w - __bfloat162float(h3));
    union { __nv_bfloat162 b2[2]; uint2 u; } th, tl;
    th.b2[0] = __halves2bfloat162(h0, h1); th.b2[1] = __halves2bfloat162(h2, h3);
    tl.b2[0] = __halves2bfloat162(l0, l1); tl.b2[1] = __halves2bfloat162(l2, l3);
    h = th.u; l = tl.u;
}

// ---------------- fused transpose + prep (one launch) ----------------
// blocks 0..63: wk -> wkT transpose ; blocks 64..128: wcvec/rvec/c0 dots
__global__ void prep_fused(const float* __restrict__ wq, const float* __restrict__ wk,
                           const float* __restrict__ bq, const float* __restrict__ bk,
                           float* __restrict__ wkT) {
    if (blockIdx.x < 64) {
        __shared__ float tile[32][33];
        int bx = (blockIdx.x & 7) * 32, by = (blockIdx.x >> 3) * 32;
        int tx = threadIdx.x & 31, ty = threadIdx.x >> 5;   // 32x8
#pragma unroll
        for (int i = 0; i < 32; i += 8)
            tile[ty + i][tx] = wk[(size_t)(by + ty + i) * HID + bx + tx];
        __syncthreads();
#pragma unroll
        for (int i = 0; i < 32; i += 8)
            wkT[(size_t)(bx + ty + i) * HID + by + tx] = tile[tx][ty + i];
        return;
    }
    int gw = ((blockIdx.x - 64) * 256 + threadIdx.x) >> 5;
    int lane = threadIdx.x & 31;
    if (gw > 2 * HID) return;
    const float* rowp;
    const float* vecp;
    if (gw < HID)            { rowp = wq + (size_t)gw * HID;          vecp = bk; }
    else if (gw < 2 * HID)   { rowp = wk + (size_t)(gw - HID) * HID;  vecp = bq; }
    else                     { rowp = bq;                             vecp = bk; }
    float acc = 0.f;
#pragma unroll
    for (int t = 0; t < HID / 32; t++)
        acc += rowp[lane + 32 * t] * vecp[lane + 32 * t];
    acc = warp_sum(acc);
    if (lane == 0) {
        if (gw < HID)          g_wcvec[gw] = acc;
        else if (gw < 2 * HID) g_rvec[gw - HID] = acc;
        else                   g_c0 = acc;
    }
}

// ---------------- tensor-core split-bf16 GEMM, fused fp32 load/convert ----------------
// (proven version; untouched)
#define ASTR 40
#define BSTR 72

template<bool BIAS, bool RELU, bool SPLITK>
__global__ __launch_bounds__(256)
void bgemm_kernel(const float* __restrict__ A, const float* __restrict__ B,
                  const float* __restrict__ bias, float* __restrict__ C,
                  int M, int N, int K, int lda)
{
    __shared__ __align__(16) __nv_bfloat16 sAh[128 * ASTR], sAl[128 * ASTR];
    __shared__ __align__(16) __nv_bfloat16 sBh[32 * BSTR],  sBl[32 * BSTR];

    const int tid  = threadIdx.x;
    const int lane = tid & 31, wid = tid >> 5;
    const int wm = wid >> 1, wn = wid & 1;
    const int row0 = blockIdx.y * 128, col0 = blockIdx.x * 64;
    const int koff = SPLITK ? blockIdx.z * K : 0;

    float acc[2][4][4];
#pragma unroll
    for (int mi = 0; mi < 2; mi++)
#pragma unroll
        for (int nj = 0; nj < 4; nj++)
#pragma unroll
            for (int q = 0; q < 4; q++) acc[mi][nj][q] = 0.f;

    int a_r[4], a_c[4], b_r[2], b_c[2];
    size_t a_off[4], b_off[2];
#pragma unroll
    for (int i = 0; i < 4; i++) {
        int idx = tid + i * 256;
        a_r[i] = idx >> 3; a_c[i] = (idx & 7) * 4;
        a_off[i] = (size_t)(row0 + a_r[i]) * lda + koff + a_c[i];
    }
#pragma unroll
    for (int i = 0; i < 2; i++) {
        int idx = tid + i * 256;
        b_r[i] = idx >> 4; b_c[i] = (idx & 15) * 4;
        b_off[i] = (size_t)(koff + b_r[i]) * N + col0 + b_c[i];
    }

    float4 pA[4], pB[2];
#pragma unroll
    for (int i = 0; i < 4; i++) pA[i] = *(const float4*)(A + a_off[i]);
#pragma unroll
    for (int i = 0; i < 2; i++) pB[i] = *(const float4*)(B + b_off[i]);

    const uint32_t sAh_u = s2u(sAh), sAl_u = s2u(sAl), sBh_u = s2u(sBh), sBl_u = s2u(sBl);
    const int a_lrow = wm * 32 + (lane & 15);
    const int a_lcol = ((lane >> 4) & 1) * 8;
    const int b_lrow = (lane & 7) + ((lane >> 3) & 1) * 8;
    const int b_lcol = wn * 32 + ((lane >> 4) & 1) * 8;

    const int NT = K / 32;
    for (int kt = 0; kt < NT; kt++) {
#pragma unroll
        for (int i = 0; i < 4; i++) {
            uint2 h, l; split4(pA[i], h, l);
            *(uint2*)&sAh[a_r[i] * ASTR + a_c[i]] = h;
            *(uint2*)&sAl[a_r[i] * ASTR + a_c[i]] = l;
        }
#pragma unroll
        for (int i = 0; i < 2; i++) {
            uint2 h, l; split4(pB[i], h, l);
            *(uint2*)&sBh[b_r[i] * BSTR + b_c[i]] = h;
            *(uint2*)&sBl[b_r[i] * BSTR + b_c[i]] = l;
        }
        __syncthreads();

        if (kt + 1 < NT) {
#pragma unroll
            for (int i = 0; i < 4; i++) pA[i] = *(const float4*)(A + a_off[i] + (size_t)(kt + 1) * 32);
#pragma unroll
            for (int i = 0; i < 2; i++) pB[i] = *(const float4*)(B + b_off[i] + (size_t)(kt + 1) * 32 * N);
        }

#pragma unroll
        for (int ks = 0; ks < 2; ks++) {
            uint32_t ah[2][4], al[2][4], bh[4][2], bl[4][2];
#pragma unroll
            for (int mi = 0; mi < 2; mi++) {
                uint32_t aoff = (uint32_t)(((a_lrow + mi * 16) * ASTR + ks * 16 + a_lcol) * 2);
                ldsm4(ah[mi][0], ah[mi][1], ah[mi][2], ah[mi][3], sAh_u + aoff);
                ldsm4(al[mi][0], al[mi][1], al[mi][2], al[mi][3], sAl_u + aoff);
            }
#pragma unroll
            for (int nj2 = 0; nj2 < 2; nj2++) {
                uint32_t boff = (uint32_t)(((ks * 16 + b_lrow) * BSTR + b_lcol + nj2 * 16) * 2);
                uint32_t t0, t1, t2, t3;
                ldsm4t(t0, t1, t2, t3, sBh_u + boff);
                bh[nj2 * 2][0] = t0; bh[nj2 * 2][1] = t1;
                bh[nj2 * 2 + 1][0] = t2; bh[nj2 * 2 + 1][1] = t3;
                ldsm4t(t0, t1, t2, t3, sBl_u + boff);
                bl[nj2 * 2][0] = t0; bl[nj2 * 2][1] = t1;
                bl[nj2 * 2 + 1][0] = t2; bl[nj2 * 2 + 1][1] = t3;
            }
#pragma unroll
            for (int mi = 0; mi < 2; mi++)
#pragma unroll
                for (int nj = 0; nj < 4; nj++) {
                    mma16816(acc[mi][nj], ah[mi], bh[nj]);
                    mma16816(acc[mi][nj], ah[mi], bl[nj]);
                    mma16816(acc[mi][nj], al[mi], bh[nj]);
                }
        }
        __syncthreads();
    }

    float* Cout = SPLITK ? C + (size_t)blockIdx.z * M * N : C;
#pragma unroll
    for (int mi = 0; mi < 2; mi++) {
        int r = row0 + wm * 32 + mi * 16 + (lane >> 2);
#pragma unroll
        for (int nj = 0; nj < 4; nj++) {
            int c = col0 + wn * 32 + nj * 8 + (lane & 3) * 2;
            float b0 = 0.f, b1 = 0.f;
            if (BIAS) { b0 = bias[c]; b1 = bias[c + 1]; }
            float v00 = acc[mi][nj][0] + b0, v01 = acc[mi][nj][1] + b1;
            float v10 = acc[mi][nj][2] + b0, v11 = acc[mi][nj][3] + b1;
            if (RELU) {
                v00 = fmaxf(v00, 0.f); v01 = fmaxf(v01, 0.f);
                v10 = fmaxf(v10, 0.f); v11 = fmaxf(v11, 0.f);
            }
            *(float2*)&Cout[(size_t)r * N + c]       = make_float2(v00, v01);
            *(float2*)&Cout[(size_t)(r + 8) * N + c] = make_float2(v10, v11);
        }
    }
}

// ---------------- mega-fused attention kernel ----------------
// block per graph. Phase 3 now: 4 thread-groups x float4 columns, smem cross-group reduce.
__global__ void score_attn_kernel(const float* __restrict__ key,
                                  const float* __restrict__ value,
                                  const float* __restrict__ smiles,
                                  const int* __restrict__ batch,
                                  float* __restrict__ att_out) {
    __shared__ float u_s[HID];
    __shared__ float es[MAXSEG];
    __shared__ float red[4][HID];
    __shared__ int seg_sh[2];
    int b = blockIdx.x, t = threadIdx.x;
    int lane = t & 31, w = t >> 5;
    const size_t STRIDE = (size_t)NB * HID;
    size_t ridx = (size_t)b * HID + t;

    if (t < 2) {
        int target = b + t;
        int lo = 0, hi = NN;
        while (lo < hi) { int mid = (lo + hi) >> 1; if (batch[mid] < target) lo = mid + 1; else hi = mid; }
        seg_sh[t] = lo;
    }
    u_s[t] = g_hp[ridx] + g_hp[ridx + STRIDE] + g_rvec[t];
    float cb = block_sum_256(smiles[ridx] * g_wcvec[t]) + g_c0;
    int s0 = seg_sh[0], s1 = seg_sh[1];
    int len = s1 - s0;

    // phase 1: per-node scores (warp per node, 8 nodes in flight)
    for (int i = s0 + w; i < s1; i += 8) {
        const float* kp = key + (size_t)i * HID;
        float acc = 0.f;
#pragma unroll
        for (int j = 0; j < 8; j++)
            acc += kp[lane + 32 * j] * u_s[lane + 32 * j];
        acc = warp_sum(acc);
        if (lane == 0) {
            float e = expf((acc + cb) * INV_SCALE);
            int idx = i - s0;
            if (idx < MAXSEG) es[idx] = e; else g_escore[i] = e;
        }
    }
    __syncthreads();

    // phase 2: denom
    float partial = 0.f;
    for (int idx = t; idx < len; idx += 256)
        partial += (idx < MAXSEG) ? es[idx] : g_escore[s0 + idx];
    float denom = block_sum_256(partial);

    // phase 3: attention output + weighted value sum (4 groups x float4)
    float invd = (len > 0) ? 1.f / denom : 0.f;
    for (int idx = t; idx < len; idx += 256)
        att_out[s0 + idx] = ((idx < MAXSEG) ? es[idx] : g_escore[s0 + idx]) * invd;

    int g = t >> 6;                 // group 0..3
    int c = (t & 63) * 4;           // columns c..c+3
    float4 a4 = make_float4(0.f, 0.f, 0.f, 0.f);
#pragma unroll 2
    for (int idx = g; idx < len; idx += 4) {
        float e = (idx < MAXSEG) ? es[idx] : g_escore[s0 + idx];
        float4 v = *(const float4*)(value + (size_t)(s0 + idx) * HID + c);
        a4.x += e * v.x; a4.y += e * v.y; a4.z += e * v.z; a4.w += e * v.w;
    }
    *(float4*)&red[g][c] = a4;
    __syncthreads();
    float sres = (red[0][t] + red[1][t] + red[2][t] + red[3][t]) * invd;
    g_s[ridx] = sres;
}

// X1 = LN(smiles + (hp[0]+hp[1]+bv))  -- Dh split-K reduction fused into LN0
__global__ void ln1_reduce(const float* __restrict__ smiles, const float* __restrict__ bv,
                           const float* __restrict__ g, const float* __restrict__ b,
                           float* __restrict__ out) {
    int row = blockIdx.x, t = threadIdx.x;
    size_t idx = (size_t)row * HID + t;
    const size_t STRIDE = (size_t)NB * HID;
    float dh = g_hp[idx] + g_hp[idx + STRIDE] + bv[t];
    float v = smiles[idx] + dh;
    float mu = block_sum_256(v) * (1.f / HID);
    float d = v - mu;
    float var = block_sum_256(d * d) * (1.f / HID);
    out[idx] = d * rsqrtf(var + 1e-5f) * g[t] + b[t];
}

// out = LN(x1 + (hp[0..3] + c2))  -- FFN2 split-K reduction fused into LN1
__global__ void ln2_reduce(const float* __restrict__ x1, const float* __restrict__ c2,
                           const float* __restrict__ g, const float* __restrict__ b,
                           float* __restrict__ out) {
    int row = blockIdx.x, t = threadIdx.x;
    size_t idx = (size_t)row * HID + t;
    const size_t STRIDE = (size_t)NB * HID;
    float h = g_hp[idx] + g_hp[idx + STRIDE] + g_hp[idx + 2 * STRIDE] + g_hp[idx + 3 * STRIDE] + c2[t];
    float v = x1[idx] + h;
    float mu = block_sum_256(v) * (1.f / HID);
    float d = v - mu;
    float var = block_sum_256(d * d) * (1.f / HID);
    out[idx] = d * rsqrtf(var + 1e-5f) * g[t] + b[t];
}

// ---------------- launcher ----------------
extern "C" void kernel_launch(void* const* d_in, const int* in_sizes, int n_in,
                              void* d_out, int out_size) {
    const float* smiles   = (const float*)d_in[0];
    const float* key_in   = (const float*)d_in[1];
    const float* value_in = (const float*)d_in[2];
    const int*   batch    = (const int*)  d_in[3];
    const float* wq   = (const float*)d_in[4];
    const float* bq   = (const float*)d_in[5];
    const float* wk   = (const float*)d_in[6];
    const float* bk   = (const float*)d_in[7];
    const float* wv   = (const float*)d_in[8];
    const float* bv   = (const float*)d_in[9];
    const float* ln0g = (const float*)d_in[10];
    const float* ln0b = (const float*)d_in[11];
    const float* ln1g = (const float*)d_in[12];
    const float* ln1b = (const float*)d_in[13];
    const float* w1   = (const float*)d_in[14];
    const float* c1   = (const float*)d_in[15];
    const float* w2   = (const float*)d_in[16];
    const float* c2   = (const float*)d_in[17];

    float* out        = (float*)d_out;
    float* out_smiles = out;
    float* out_att    = out + (size_t)NB * HID;

    float *WkT, *M, *S, *X1, *H1, *Hp;
    cudaGetSymbolAddress((void**)&WkT, g_wkT);
    cudaGetSymbolAddress((void**)&M,   g_M);
    cudaGetSymbolAddress((void**)&S,   g_s);
    cudaGetSymbolAddress((void**)&X1,  g_x1);
    cudaGetSymbolAddress((void**)&H1,  g_h1);
    cudaGetSymbolAddress((void**)&Hp,  g_hp);

    // launches: prep(1), M(2), U(3), score_attn(4 = ncu profiled slot)
    prep_fused<<<129, 256>>>(wq, wk, bq, bk, WkT);
    // M = wq @ wk^T (small)
    bgemm_kernel<false, false, false><<<dim3(HID / 64, HID / 128), 256>>>(wq, WkT, nullptr, M, HID, HID, HID, HID);
    // U partials = smiles @ M (split-K=2, 256 CTAs)
    bgemm_kernel<false, false, true><<<dim3(HID / 64, NB / 128, 2), 256>>>(smiles, M, nullptr, Hp, NB, HID, HID / 2, HID);

    // mega-fused: seg search + U-reduce + c + score + softmax + value sum
    score_attn_kernel<<<NB, 256>>>(key_in, value_in, smiles, batch, out_att);

    // Dh partials = S @ wv (split-K=2, 256 CTAs); X1 = LN(smiles + Dh + bv)
    bgemm_kernel<false, false, true><<<dim3(HID / 64, NB / 128, 2), 256>>>(S, wv, nullptr, Hp, NB, HID, HID / 2, HID);
    ln1_reduce<<<NB, 256>>>(smiles, bv, ln0g, ln0b, X1);

    // FFN1: H1 = relu(X1 @ w1 + c1)
    bgemm_kernel<true, true, false><<<dim3(HF4 / 64, NB / 128), 256>>>(X1, w1, c1, H1, NB, HF4, HID, HID);
    // FFN2 split-K=4: partials Hp[z] = H1 @ w2[z-slice]
    bgemm_kernel<false, false, true><<<dim3(HID / 64, NB / 128, 4), 256>>>(H1, w2, nullptr, Hp, NB, HID, HF4 / 4, HF4);
    // reduce partials + c2, add X1, LN -> out
    ln2_reduce<<<NB, 256>>>(X1, c2, ln1g, ln1b, out_smiles);
}

// round 16
// speedup vs baseline: 1.0920x; 1.0920x over previous
#include <cuda_runtime.h>
#include <cuda_bf16.h>
#include <math.h>
#include <stdint.h>

#define HID   256
#define NB    4096
#define NN    204800
#define HF4   1024
#define INV_SCALE 0.17677669529663687f
#define MAXSEG 1024

// ---------------- scratch (static device globals; no allocation) ----------------
__device__ float g_wkT[HID * HID];
__device__ float g_M  [HID * HID];
__device__ float g_rvec[HID];
__device__ float g_wcvec[HID];
__device__ float g_c0;
__device__ float g_escore[NN];        // overflow fallback only (len > MAXSEG)
__device__ float g_s [NB * HID];
__device__ float g_x1[NB * HID];
__device__ float g_h1[NB * HF4];
__device__ float g_hp[4 * NB * HID];  // split-K partials (U, Dh, FFN2 - sequential reuse)

// ---------------- helpers ----------------
__device__ __forceinline__ float warp_sum(float v) {
#pragma unroll
    for (int o = 16; o; o >>= 1) v += __shfl_xor_sync(0xffffffffu, v, o);
    return v;
}

__device__ __forceinline__ float block_sum_256(float v) {
    __shared__ float sh[8];
    int lane = threadIdx.x & 31, w = threadIdx.x >> 5;
    v = warp_sum(v);
    if (lane == 0) sh[w] = v;
    __syncthreads();
    float r = (lane < 8) ? sh[lane] : 0.f;
    r = warp_sum(r);
    __syncthreads();
    return r;
}

__device__ __forceinline__ uint32_t s2u(const void* p) {
    return (uint32_t)__cvta_generic_to_shared(p);
}

__device__ __forceinline__ void ldsm4(uint32_t& r0, uint32_t& r1, uint32_t& r2, uint32_t& r3, uint32_t addr) {
    asm volatile("ldmatrix.sync.aligned.m8n8.x4.shared.b16 {%0,%1,%2,%3}, [%4];"
                 : "=r"(r0), "=r"(r1), "=r"(r2), "=r"(r3) : "r"(addr));
}
__device__ __forceinline__ void ldsm4t(uint32_t& r0, uint32_t& r1, uint32_t& r2, uint32_t& r3, uint32_t addr) {
    asm volatile("ldmatrix.sync.aligned.m8n8.x4.trans.shared.b16 {%0,%1,%2,%3}, [%4];"
                 : "=r"(r0), "=r"(r1), "=r"(r2), "=r"(r3) : "r"(addr));
}
__device__ __forceinline__ void mma16816(float* c, const uint32_t* a, const uint32_t* b) {
    asm volatile("mma.sync.aligned.m16n8k16.row.col.f32.bf16.bf16.f32 "
                 "{%0,%1,%2,%3},{%4,%5,%6,%7},{%8,%9},{%0,%1,%2,%3};"
                 : "+f"(c[0]), "+f"(c[1]), "+f"(c[2]), "+f"(c[3])
                 : "r"(a[0]), "r"(a[1]), "r"(a[2]), "r"(a[3]), "r"(b[0]), "r"(b[1]));
}

__device__ __forceinline__ void split4(float4 v, uint2& h, uint2& l) {
    __nv_bfloat16 h0 = __float2bfloat16(v.x), h1 = __float2bfloat16(v.y);
    __nv_bfloat16 h2 = __float2bfloat16(v.z), h3 = __float2bfloat16(v.w);
    __nv_bfloat16 l0 = __float2bfloat16(v.x - __bfloat162float(h0));
    __nv_bfloat16 l1 = __float2bfloat16(v.y - __bfloat162float(h1));
    __nv_bfloat16 l2 = __float2bfloat16(v.z - __bfloat162float(h2));
    __nv_bfloat16 l3 = __float2bfloat16(v.w - __bfloat162float(h3));
    union { __nv_bfloat162 b2[2]; uint2 u; } th, tl;
    th.b2[0] = __halves2bfloat162(h0, h1); th.b2[1] = __halves2bfloat162(h2, h3);
    tl.b2[0] = __halves2bfloat162(l0, l1); tl.b2[1] = __halves2bfloat162(l2, l3);
    h = th.u; l = tl.u;
}

// ---------------- fused transpose + prep (one launch) ----------------
__global__ void prep_fused(const float* __restrict__ wq, const float* __restrict__ wk,
                           const float* __restrict__ bq, const float* __restrict__ bk,
                           float* __restrict__ wkT) {
    if (blockIdx.x < 64) {
        __shared__ float tile[32][33];
        int bx = (blockIdx.x & 7) * 32, by = (blockIdx.x >> 3) * 32;
        int tx = threadIdx.x & 31, ty = threadIdx.x >> 5;   // 32x8
#pragma unroll
        for (int i = 0; i < 32; i += 8)
            tile[ty + i][tx] = wk[(size_t)(by + ty + i) * HID + bx + tx];
        __syncthreads();
#pragma unroll
        for (int i = 0; i < 32; i += 8)
            wkT[(size_t)(bx + ty + i) * HID + by + tx] = tile[tx][ty + i];
        return;
    }
    int gw = ((blockIdx.x - 64) * 256 + threadIdx.x) >> 5;
    int lane = threadIdx.x & 31;
    if (gw > 2 * HID) return;
    const float* rowp;
    const float* vecp;
    if (gw < HID)            { rowp = wq + (size_t)gw * HID;          vecp = bk; }
    else if (gw < 2 * HID)   { rowp = wk + (size_t)(gw - HID) * HID;  vecp = bq; }
    else                     { rowp = bq;                             vecp = bk; }
    float acc = 0.f;
#pragma unroll
    for (int t = 0; t < HID / 32; t++)
        acc += rowp[lane + 32 * t] * vecp[lane + 32 * t];
    acc = warp_sum(acc);
    if (lane == 0) {
        if (gw < HID)          g_wcvec[gw] = acc;
        else if (gw < 2 * HID) g_rvec[gw - HID] = acc;
        else                   g_c0 = acc;
    }
}

// ---------------- tensor-core split-bf16 GEMM, fused fp32 load/convert ----------------
// (proven version; untouched)
#define ASTR 40
#define BSTR 72

template<bool BIAS, bool RELU, bool SPLITK>
__global__ __launch_bounds__(256)
void bgemm_kernel(const float* __restrict__ A, const float* __restrict__ B,
                  const float* __restrict__ bias, float* __restrict__ C,
                  int M, int N, int K, int lda)
{
    __shared__ __align__(16) __nv_bfloat16 sAh[128 * ASTR], sAl[128 * ASTR];
    __shared__ __align__(16) __nv_bfloat16 sBh[32 * BSTR],  sBl[32 * BSTR];

    const int tid  = threadIdx.x;
    const int lane = tid & 31, wid = tid >> 5;
    const int wm = wid >> 1, wn = wid & 1;
    const int row0 = blockIdx.y * 128, col0 = blockIdx.x * 64;
    const int koff = SPLITK ? blockIdx.z * K : 0;

    float acc[2][4][4];
#pragma unroll
    for (int mi = 0; mi < 2; mi++)
#pragma unroll
        for (int nj = 0; nj < 4; nj++)
#pragma unroll
            for (int q = 0; q < 4; q++) acc[mi][nj][q] = 0.f;

    int a_r[4], a_c[4], b_r[2], b_c[2];
    size_t a_off[4], b_off[2];
#pragma unroll
    for (int i = 0; i < 4; i++) {
        int idx = tid + i * 256;
        a_r[i] = idx >> 3; a_c[i] = (idx & 7) * 4;
        a_off[i] = (size_t)(row0 + a_r[i]) * lda + koff + a_c[i];
    }
#pragma unroll
    for (int i = 0; i < 2; i++) {
        int idx = tid + i * 256;
        b_r[i] = idx >> 4; b_c[i] = (idx & 15) * 4;
        b_off[i] = (size_t)(koff + b_r[i]) * N + col0 + b_c[i];
    }

    float4 pA[4], pB[2];
#pragma unroll
    for (int i = 0; i < 4; i++) pA[i] = *(const float4*)(A + a_off[i]);
#pragma unroll
    for (int i = 0; i < 2; i++) pB[i] = *(const float4*)(B + b_off[i]);

    const uint32_t sAh_u = s2u(sAh), sAl_u = s2u(sAl), sBh_u = s2u(sBh), sBl_u = s2u(sBl);
    const int a_lrow = wm * 32 + (lane & 15);
    const int a_lcol = ((lane >> 4) & 1) * 8;
    const int b_lrow = (lane & 7) + ((lane >> 3) & 1) * 8;
    const int b_lcol = wn * 32 + ((lane >> 4) & 1) * 8;

    const int NT = K / 32;
    for (int kt = 0; kt < NT; kt++) {
#pragma unroll
        for (int i = 0; i < 4; i++) {
            uint2 h, l; split4(pA[i], h, l);
            *(uint2*)&sAh[a_r[i] * ASTR + a_c[i]] = h;
            *(uint2*)&sAl[a_r[i] * ASTR + a_c[i]] = l;
        }
#pragma unroll
        for (int i = 0; i < 2; i++) {
            uint2 h, l; split4(pB[i], h, l);
            *(uint2*)&sBh[b_r[i] * BSTR + b_c[i]] = h;
            *(uint2*)&sBl[b_r[i] * BSTR + b_c[i]] = l;
        }
        __syncthreads();

        if (kt + 1 < NT) {
#pragma unroll
            for (int i = 0; i < 4; i++) pA[i] = *(const float4*)(A + a_off[i] + (size_t)(kt + 1) * 32);
#pragma unroll
            for (int i = 0; i < 2; i++) pB[i] = *(const float4*)(B + b_off[i] + (size_t)(kt + 1) * 32 * N);
        }

#pragma unroll
        for (int ks = 0; ks < 2; ks++) {
            uint32_t ah[2][4], al[2][4], bh[4][2], bl[4][2];
#pragma unroll
            for (int mi = 0; mi < 2; mi++) {
                uint32_t aoff = (uint32_t)(((a_lrow + mi * 16) * ASTR + ks * 16 + a_lcol) * 2);
                ldsm4(ah[mi][0], ah[mi][1], ah[mi][2], ah[mi][3], sAh_u + aoff);
                ldsm4(al[mi][0], al[mi][1], al[mi][2], al[mi][3], sAl_u + aoff);
            }
#pragma unroll
            for (int nj2 = 0; nj2 < 2; nj2++) {
                uint32_t boff = (uint32_t)(((ks * 16 + b_lrow) * BSTR + b_lcol + nj2 * 16) * 2);
                uint32_t t0, t1, t2, t3;
                ldsm4t(t0, t1, t2, t3, sBh_u + boff);
                bh[nj2 * 2][0] = t0; bh[nj2 * 2][1] = t1;
                bh[nj2 * 2 + 1][0] = t2; bh[nj2 * 2 + 1][1] = t3;
                ldsm4t(t0, t1, t2, t3, sBl_u + boff);
                bl[nj2 * 2][0] = t0; bl[nj2 * 2][1] = t1;
                bl[nj2 * 2 + 1][0] = t2; bl[nj2 * 2 + 1][1] = t3;
            }
#pragma unroll
            for (int mi = 0; mi < 2; mi++)
#pragma unroll
                for (int nj = 0; nj < 4; nj++) {
                    mma16816(acc[mi][nj], ah[mi], bh[nj]);
                    mma16816(acc[mi][nj], ah[mi], bl[nj]);
                    mma16816(acc[mi][nj], al[mi], bh[nj]);
                }
        }
        __syncthreads();
    }

    float* Cout = SPLITK ? C + (size_t)blockIdx.z * M * N : C;
#pragma unroll
    for (int mi = 0; mi < 2; mi++) {
        int r = row0 + wm * 32 + mi * 16 + (lane >> 2);
#pragma unroll
        for (int nj = 0; nj < 4; nj++) {
            int c = col0 + wn * 32 + nj * 8 + (lane & 3) * 2;
            float b0 = 0.f, b1 = 0.f;
            if (BIAS) { b0 = bias[c]; b1 = bias[c + 1]; }
            float v00 = acc[mi][nj][0] + b0, v01 = acc[mi][nj][1] + b1;
            float v10 = acc[mi][nj][2] + b0, v11 = acc[mi][nj][3] + b1;
            if (RELU) {
                v00 = fmaxf(v00, 0.f); v01 = fmaxf(v01, 0.f);
                v10 = fmaxf(v10, 0.f); v11 = fmaxf(v11, 0.f);
            }
            *(float2*)&Cout[(size_t)r * N + c]       = make_float2(v00, v01);
            *(float2*)&Cout[(size_t)(r + 8) * N + c] = make_float2(v10, v11);
        }
    }
}

// ---------------- single-pass fused attention kernel ----------------
// block per graph. ONE streaming pass: per node, load key row AND value row,
// dot -> e -> accumulate e*v into per-warp registers; denom + scale at the end.
__global__ void score_attn_kernel(const float* __restrict__ key,
                                  const float* __restrict__ value,
                                  const float* __restrict__ smiles,
                                  const int* __restrict__ batch,
                                  float* __restrict__ att_out) {
    __shared__ float u_s[HID];
    __shared__ float es[MAXSEG];
    __shared__ float red[8][HID];
    __shared__ int seg_sh[2];
    int b = blockIdx.x, t = threadIdx.x;
    int lane = t & 31, w = t >> 5;
    const size_t STRIDE = (size_t)NB * HID;
    size_t ridx = (size_t)b * HID + t;

    // segment bounds via in-block binary search (threads 0,1)
    if (t < 2) {
        int target = b + t;
        int lo = 0, hi = NN;
        while (lo < hi) { int mid = (lo + hi) >> 1; if (batch[mid] < target) lo = mid + 1; else hi = mid; }
        seg_sh[t] = lo;
    }
    // u[b] = hp0 + hp1 + rvec  (U split-K reduction fused into smem load)
    u_s[t] = g_hp[ridx] + g_hp[ridx + STRIDE] + g_rvec[t];
    // c[b] (block reduction; its internal syncs also publish u_s/seg_sh)
    float cb = block_sum_256(smiles[ridx] * g_wcvec[t]) + g_c0;
    int s0 = seg_sh[0], s1 = seg_sh[1];
    int len = s1 - s0;

    // single pass: warp per node (8 nodes in flight), 16 loads/lane in flight
    float acc[8];
#pragma unroll
    for (int j = 0; j < 8; j++) acc[j] = 0.f;

    for (int i = s0 + w; i < s1; i += 8) {
        const float* kp = key   + (size_t)i * HID;
        const float* vp = value + (size_t)i * HID;
        float kv[8], vv[8];
#pragma unroll
        for (int j = 0; j < 8; j++) kv[j] = kp[lane + 32 * j];
#pragma unroll
        for (int j = 0; j < 8; j++) vv[j] = vp[lane + 32 * j];
        float d = 0.f;
#pragma unroll
        for (int j = 0; j < 8; j++) d += kv[j] * u_s[lane + 32 * j];
        d = warp_sum(d);
        float e = expf((d + cb) * INV_SCALE);
        int idx = i - s0;
        if (lane == 0) {
            if (idx < MAXSEG) es[idx] = e; else g_escore[i] = e;
        }
#pragma unroll
        for (int j = 0; j < 8; j++) acc[j] += e * vv[j];
    }
    __syncthreads();

    // denom
    float partial = 0.f;
    for (int idx = t; idx < len; idx += 256)
        partial += (idx < MAXSEG) ? es[idx] : g_escore[s0 + idx];
    float denom = block_sum_256(partial);
    float invd = (len > 0) ? 1.f / denom : 0.f;

    // attention output
    for (int idx = t; idx < len; idx += 256)
        att_out[s0 + idx] = ((idx < MAXSEG) ? es[idx] : g_escore[s0 + idx]) * invd;

    // cross-warp reduce of value partials, then scale
#pragma unroll
    for (int j = 0; j < 8; j++) red[w][lane + 32 * j] = acc[j];
    __syncthreads();
    float s = 0.f;
#pragma unroll
    for (int ww = 0; ww < 8; ww++) s += red[ww][t];
    g_s[ridx] = s * invd;
}

// X1 = LN(smiles + (hp[0]+hp[1]+bv))  -- Dh split-K reduction fused into LN0
__global__ void ln1_reduce(const float* __restrict__ smiles, const float* __restrict__ bv,
                           const float* __restrict__ g, const float* __restrict__ b,
                           float* __restrict__ out) {
    int row = blockIdx.x, t = threadIdx.x;
    size_t idx = (size_t)row * HID + t;
    const size_t STRIDE = (size_t)NB * HID;
    float dh = g_hp[idx] + g_hp[idx + STRIDE] + bv[t];
    float v = smiles[idx] + dh;
    float mu = block_sum_256(v) * (1.f / HID);
    float d = v - mu;
    float var = block_sum_256(d * d) * (1.f / HID);
    out[idx] = d * rsqrtf(var + 1e-5f) * g[t] + b[t];
}

// out = LN(x1 + (hp[0..3] + c2))  -- FFN2 split-K reduction fused into LN1
__global__ void ln2_reduce(const float* __restrict__ x1, const float* __restrict__ c2,
                           const float* __restrict__ g, const float* __restrict__ b,
                           float* __restrict__ out) {
    int row = blockIdx.x, t = threadIdx.x;
    size_t idx = (size_t)row * HID + t;
    const size_t STRIDE = (size_t)NB * HID;
    float h = g_hp[idx] + g_hp[idx + STRIDE] + g_hp[idx + 2 * STRIDE] + g_hp[idx + 3 * STRIDE] + c2[t];
    float v = x1[idx] + h;
    float mu = block_sum_256(v) * (1.f / HID);
    float d = v - mu;
    float var = block_sum_256(d * d) * (1.f / HID);
    out[idx] = d * rsqrtf(var + 1e-5f) * g[t] + b[t];
}

// ---------------- launcher ----------------
extern "C" void kernel_launch(void* const* d_in, const int* in_sizes, int n_in,
                              void* d_out, int out_size) {
    const float* smiles   = (const float*)d_in[0];
    const float* key_in   = (const float*)d_in[1];
    const float* value_in = (const float*)d_in[2];
    const int*   batch    = (const int*)  d_in[3];
    const float* wq   = (const float*)d_in[4];
    const float* bq   = (const float*)d_in[5];
    const float* wk   = (const float*)d_in[6];
    const float* bk   = (const float*)d_in[7];
    const float* wv   = (const float*)d_in[8];
    const float* bv   = (const float*)d_in[9];
    const float* ln0g = (const float*)d_in[10];
    const float* ln0b = (const float*)d_in[11];
    const float* ln1g = (const float*)d_in[12];
    const float* ln1b = (const float*)d_in[13];
    const float* w1   = (const float*)d_in[14];
    const float* c1   = (const float*)d_in[15];
    const float* w2   = (const float*)d_in[16];
    const float* c2   = (const float*)d_in[17];

    float* out        = (float*)d_out;
    float* out_smiles = out;
    float* out_att    = out + (size_t)NB * HID;

    float *WkT, *M, *S, *X1, *H1, *Hp;
    cudaGetSymbolAddress((void**)&WkT, g_wkT);
    cudaGetSymbolAddress((void**)&M,   g_M);
    cudaGetSymbolAddress((void**)&S,   g_s);
    cudaGetSymbolAddress((void**)&X1,  g_x1);
    cudaGetSymbolAddress((void**)&H1,  g_h1);
    cudaGetSymbolAddress((void**)&Hp,  g_hp);

    // launches: prep(1), M(2), U(3), score_attn(4 = ncu profiled slot)
    prep_fused<<<129, 256>>>(wq, wk, bq, bk, WkT);
    // M = wq @ wk^T (small)
    bgemm_kernel<false, false, false><<<dim3(HID / 64, HID / 128), 256>>>(wq, WkT, nullptr, M, HID, HID, HID, HID);
    // U partials = smiles @ M (split-K=2, 256 CTAs)
    bgemm_kernel<false, false, true><<<dim3(HID / 64, NB / 128, 2), 256>>>(smiles, M, nullptr, Hp, NB, HID, HID / 2, HID);

    // single-pass fused attention
    score_attn_kernel<<<NB, 256>>>(key_in, value_in, smiles, batch, out_att);

    // Dh partials = S @ wv (split-K=2, 256 CTAs); X1 = LN(smiles + Dh + bv)
    bgemm_kernel<false, false, true><<<dim3(HID / 64, NB / 128, 2), 256>>>(S, wv, nullptr, Hp, NB, HID, HID / 2, HID);
    ln1_reduce<<<NB, 256>>>(smiles, bv, ln0g, ln0b, X1);

    // FFN1: H1 = relu(X1 @ w1 + c1)
    bgemm_kernel<true, true, false><<<dim3(HF4 / 64, NB / 128), 256>>>(X1, w1, c1, H1, NB, HF4, HID, HID);
    // FFN2 split-K=4: partials Hp[z] = H1 @ w2[z-slice]
    bgemm_kernel<false, false, true><<<dim3(HID / 64, NB / 128, 4), 256>>>(H1, w2, nullptr, Hp, NB, HID, HF4 / 4, HF4);
    // reduce partials + c2, add X1, LN -> out
    ln2_reduce<<<NB, 256>>>(X1, c2, ln1g, ln1b, out_smiles);
}